// round 6
// baseline (speedup 1.0000x reference)
#include <cuda_runtime.h>
#include <cstdint>

// Scratch: per-node projection (pu0, pu1, pv0, pv1). 50000 * 16B = 800 KB.
#define MAX_NODES 131072
__device__ float4 g_node_proj[MAX_NODES];

#define D_DIM 128
#define E_DIM 64

// ---------------------------------------------------------------------------
// Kernel 1: proj[n] = (nf[n]@Wu, nf[n]@Wv). 16 lanes per node, register weights.
__global__ void node_proj_kernel(const float* __restrict__ nf,
                                 const float* __restrict__ W,  // [2D+E_DIM, 2]
                                 int n_nodes) {
    int gid = blockIdx.x * blockDim.x + threadIdx.x;
    int node = gid >> 4;
    int lane16 = gid & 15;
    bool valid = (node < n_nodes);

    const float2* W2 = reinterpret_cast<const float2*>(W);

    float4 wu_lo0 = *reinterpret_cast<const float4*>(&W2[4 * lane16]);
    float4 wu_lo1 = *reinterpret_cast<const float4*>(&W2[4 * lane16 + 2]);
    float4 wu_hi0 = *reinterpret_cast<const float4*>(&W2[64 + 4 * lane16]);
    float4 wu_hi1 = *reinterpret_cast<const float4*>(&W2[64 + 4 * lane16 + 2]);
    float4 wv_lo0 = *reinterpret_cast<const float4*>(&W2[128 + 4 * lane16]);
    float4 wv_lo1 = *reinterpret_cast<const float4*>(&W2[128 + 4 * lane16 + 2]);
    float4 wv_hi0 = *reinterpret_cast<const float4*>(&W2[192 + 4 * lane16]);
    float4 wv_hi1 = *reinterpret_cast<const float4*>(&W2[192 + 4 * lane16 + 2]);

    float4 a = make_float4(0.f, 0.f, 0.f, 0.f);
    float4 c = make_float4(0.f, 0.f, 0.f, 0.f);
    if (valid) {
        const float4* row = reinterpret_cast<const float4*>(nf + (size_t)node * D_DIM);
        a = __ldcs(row + lane16);
        c = __ldcs(row + lane16 + 16);
    }

    float pu0, pu1, pv0, pv1;
    pu0 = a.x * wu_lo0.x;            pu1 = a.x * wu_lo0.y;
    pv0 = a.x * wv_lo0.x;            pv1 = a.x * wv_lo0.y;
    pu0 = fmaf(a.y, wu_lo0.z, pu0);  pu1 = fmaf(a.y, wu_lo0.w, pu1);
    pv0 = fmaf(a.y, wv_lo0.z, pv0);  pv1 = fmaf(a.y, wv_lo0.w, pv1);
    pu0 = fmaf(a.z, wu_lo1.x, pu0);  pu1 = fmaf(a.z, wu_lo1.y, pu1);
    pv0 = fmaf(a.z, wv_lo1.x, pv0);  pv1 = fmaf(a.z, wv_lo1.y, pv1);
    pu0 = fmaf(a.w, wu_lo1.z, pu0);  pu1 = fmaf(a.w, wu_lo1.w, pu1);
    pv0 = fmaf(a.w, wv_lo1.z, pv0);  pv1 = fmaf(a.w, wv_lo1.w, pv1);
    pu0 = fmaf(c.x, wu_hi0.x, pu0);  pu1 = fmaf(c.x, wu_hi0.y, pu1);
    pv0 = fmaf(c.x, wv_hi0.x, pv0);  pv1 = fmaf(c.x, wv_hi0.y, pv1);
    pu0 = fmaf(c.y, wu_hi0.z, pu0);  pu1 = fmaf(c.y, wu_hi0.w, pu1);
    pv0 = fmaf(c.y, wv_hi0.z, pv0);  pv1 = fmaf(c.y, wv_hi0.w, pv1);
    pu0 = fmaf(c.z, wu_hi1.x, pu0);  pu1 = fmaf(c.z, wu_hi1.y, pu1);
    pv0 = fmaf(c.z, wv_hi1.x, pv0);  pv1 = fmaf(c.z, wv_hi1.y, pv1);
    pu0 = fmaf(c.w, wu_hi1.z, pu0);  pu1 = fmaf(c.w, wu_hi1.w, pu1);
    pv0 = fmaf(c.w, wv_hi1.z, pv0);  pv1 = fmaf(c.w, wv_hi1.w, pv1);

#pragma unroll
    for (int off = 8; off; off >>= 1) {
        pu0 += __shfl_xor_sync(0xffffffffu, pu0, off);
        pu1 += __shfl_xor_sync(0xffffffffu, pu1, off);
        pv0 += __shfl_xor_sync(0xffffffffu, pv0, off);
        pv1 += __shfl_xor_sync(0xffffffffu, pv1, off);
    }
    if (valid && lane16 == 0) g_node_proj[node] = make_float4(pu0, pu1, pv0, pv1);
}

// ---------------------------------------------------------------------------
// Kernel 2: 4 lanes per edge, 2 edge-streams per group (A/B), deep pipeline.
// out[e] = proj[src[e]].(x,y) + proj[dst[e]].(z,w) + ef[e]@We + b

__device__ __forceinline__ void dot16(float& s0, float& s1,
                                      const float4& v0, const float4& v1,
                                      const float4& v2, const float4& v3,
                                      const float2* __restrict__ w) {
    float x0, x1, y0, y1;
    x0 = v0.x * w[0].x;              x1 = v0.x * w[0].y;
    y0 = v2.x * w[8].x;              y1 = v2.x * w[8].y;
    x0 = fmaf(v0.y, w[1].x, x0);     x1 = fmaf(v0.y, w[1].y, x1);
    y0 = fmaf(v2.y, w[9].x, y0);     y1 = fmaf(v2.y, w[9].y, y1);
    x0 = fmaf(v0.z, w[2].x, x0);     x1 = fmaf(v0.z, w[2].y, x1);
    y0 = fmaf(v2.z, w[10].x, y0);    y1 = fmaf(v2.z, w[10].y, y1);
    x0 = fmaf(v0.w, w[3].x, x0);     x1 = fmaf(v0.w, w[3].y, x1);
    y0 = fmaf(v2.w, w[11].x, y0);    y1 = fmaf(v2.w, w[11].y, y1);
    x0 = fmaf(v1.x, w[4].x, x0);     x1 = fmaf(v1.x, w[4].y, x1);
    y0 = fmaf(v3.x, w[12].x, y0);    y1 = fmaf(v3.x, w[12].y, y1);
    x0 = fmaf(v1.y, w[5].x, x0);     x1 = fmaf(v1.y, w[5].y, x1);
    y0 = fmaf(v3.y, w[13].x, y0);    y1 = fmaf(v3.y, w[13].y, y1);
    x0 = fmaf(v1.z, w[6].x, x0);     x1 = fmaf(v1.z, w[6].y, x1);
    y0 = fmaf(v3.z, w[14].x, y0);    y1 = fmaf(v3.z, w[14].y, y1);
    x0 = fmaf(v1.w, w[7].x, x0);     x1 = fmaf(v1.w, w[7].y, x1);
    y0 = fmaf(v3.w, w[15].x, y0);    y1 = fmaf(v3.w, w[15].y, y1);
    s0 = x0 + y0;
    s1 = x1 + y1;
}

__device__ __forceinline__ void ef_load(float4& d0, float4& d1, float4& d2, float4& d3,
                                        const float* __restrict__ ef,
                                        int e, int last, int lane4) {
    int ec = e > last ? last : e;
    const float4* r = reinterpret_cast<const float4*>(ef) + (size_t)ec * 16 + lane4;
    d0 = __ldcs(r);
    d1 = __ldcs(r + 4);
    d2 = __ldcs(r + 8);
    d3 = __ldcs(r + 12);
}

__device__ __forceinline__ void idx_load(int& s, int& d,
                                         const int* __restrict__ src,
                                         const int* __restrict__ dst,
                                         int e, int last) {
    int ec = e > last ? last : e;
    s = __ldcs(src + ec);
    d = __ldcs(dst + ec);
}

__device__ __forceinline__ void proj_gather(float2& pu, float2& pv, int s, int d) {
    const float2* ps = reinterpret_cast<const float2*>(&g_node_proj[s]);
    const float2* pd = reinterpret_cast<const float2*>(&g_node_proj[d]);
    pu = __ldcg(ps);       // src proj (pu0, pu1)
    pv = __ldcg(pd + 1);   // dst proj (pv0, pv1)
}

__global__ __launch_bounds__(256, 3)
void edge_score_kernel(const float* __restrict__ ef,
                       const int* __restrict__ src,
                       const int* __restrict__ dst,
                       const float* __restrict__ W,
                       const float* __restrict__ b,
                       float2* __restrict__ out,
                       int n_edges) {
    const int lane4 = threadIdx.x & 3;
    const float2* W2 = reinterpret_cast<const float2*>(W);

    float2 w[16];
#pragma unroll
    for (int i = 0; i < 4; i++) {
        int kb = 2 * D_DIM + 4 * (lane4 + 4 * i);
        float4 p0 = *reinterpret_cast<const float4*>(&W2[kb]);
        float4 p1 = *reinterpret_cast<const float4*>(&W2[kb + 2]);
        w[4 * i + 0] = make_float2(p0.x, p0.y);
        w[4 * i + 1] = make_float2(p0.z, p0.w);
        w[4 * i + 2] = make_float2(p1.x, p1.y);
        w[4 * i + 3] = make_float2(p1.z, p1.w);
    }
    const float b0 = b[0], b1 = b[1];

    const int G = (gridDim.x * blockDim.x) >> 2;
    const int group = (blockIdx.x * blockDim.x + threadIdx.x) >> 2;
    const int last = n_edges - 1;

    int eA = group;           // A stream: eA, eA+2G, ...; B stream: eA+G, ...
    int wc = group & ~7;      // warp-uniform cursor (groups in a warp are consecutive)

    // ---- Prologue ----
    float4 a0, a1, a2, a3;    // ef stage A
    float4 c0, c1, c2, c3;    // ef stage B
    ef_load(a0, a1, a2, a3, ef, eA, last, lane4);
    ef_load(c0, c1, c2, c3, ef, eA + G, last, lane4);

    float2 puA, pvA, puB, pvB;   // proj for current A/B edges (arrived)
    {
        int s0i, d0i, s1i, d1i;
        idx_load(s0i, d0i, src, dst, eA, last);
        idx_load(s1i, d1i, src, dst, eA + G, last);
        proj_gather(puA, pvA, s0i, d0i);
        proj_gather(puB, pvB, s1i, d1i);
    }
    int siC, diC, siD, diD;      // idx in flight for eA+2G (A) and eA+3G (B)
    idx_load(siC, diC, src, dst, eA + 2 * G, last);
    idx_load(siD, diD, src, dst, eA + 3 * G, last);

    while (wc < n_edges) {
        int eB = eA + G;

        // ======== A half: consume eA ========
        // Gather proj for eA+2G (idx arrived 1 pass ago); overlaps compute below.
        float2 puA2, pvA2;
        proj_gather(puA2, pvA2, siC, diC);
        // Refill A idx stream: eA+4G (consumed by the gather in the next pass).
        idx_load(siC, diC, src, dst, eA + 4 * G, last);

        float s0, s1;
        dot16(s0, s1, a0, a1, a2, a3, w);
        s0 += __shfl_xor_sync(0xffffffffu, s0, 1);
        s1 += __shfl_xor_sync(0xffffffffu, s1, 1);
        s0 += __shfl_xor_sync(0xffffffffu, s0, 2);
        s1 += __shfl_xor_sync(0xffffffffu, s1, 2);
        if (lane4 == 0 && eA < n_edges)
            __stcs(&out[eA], make_float2(s0 + puA.x + pvA.x + b0,
                                         s1 + puA.y + pvA.y + b1));
        // Refill ef stage A with eA+2G (consumed next pass).
        ef_load(a0, a1, a2, a3, ef, eA + 2 * G, last, lane4);
        puA = puA2; pvA = pvA2;

        // ======== B half: consume eB ========
        float2 puB2, pvB2;
        proj_gather(puB2, pvB2, siD, diD);
        idx_load(siD, diD, src, dst, eB + 4 * G, last);

        dot16(s0, s1, c0, c1, c2, c3, w);
        s0 += __shfl_xor_sync(0xffffffffu, s0, 1);
        s1 += __shfl_xor_sync(0xffffffffu, s1, 1);
        s0 += __shfl_xor_sync(0xffffffffu, s0, 2);
        s1 += __shfl_xor_sync(0xffffffffu, s1, 2);
        if (lane4 == 0 && eB < n_edges)
            __stcs(&out[eB], make_float2(s0 + puB.x + pvB.x + b0,
                                         s1 + puB.y + pvB.y + b1));
        ef_load(c0, c1, c2, c3, ef, eB + 2 * G, last, lane4);
        puB = puB2; pvB = pvB2;

        eA += 2 * G;
        wc += 2 * G;
    }
}

extern "C" void kernel_launch(void* const* d_in, const int* in_sizes, int n_in,
                              void* d_out, int out_size) {
    const float* node_feats = (const float*)d_in[0];
    const float* edge_feats = (const float*)d_in[1];
    const int*   src        = (const int*)d_in[2];
    const int*   dst        = (const int*)d_in[3];
    const float* W          = (const float*)d_in[4];
    const float* b          = (const float*)d_in[5];
    float2* out = (float2*)d_out;

    int n_nodes = in_sizes[0] / D_DIM;
    int n_edges = in_sizes[2];

    // Kernel 1: 16 lanes per node, 16 nodes per 256-thread block.
    {
        int threads = 256;
        int nodes_per_block = threads / 16;
        int blocks = (n_nodes + nodes_per_block - 1) / nodes_per_block;
        node_proj_kernel<<<blocks, threads>>>(node_feats, W, n_nodes);
    }

    // Kernel 2: 4 lanes per edge, A/B dual-stream pipelined grid-stride.
    {
        int threads = 256;
        int groups_per_block = threads / 4;              // 64 groups/block
        int blocks = 1480;
        long long need = ((long long)n_edges + 2LL * groups_per_block - 1)
                         / (2LL * groups_per_block);
        if (blocks > need) blocks = (int)need;
        if (blocks < 1) blocks = 1;
        edge_score_kernel<<<blocks, threads>>>(edge_feats, src, dst, W, b,
                                               out, n_edges);
    }
}

// round 7
// speedup vs baseline: 1.1980x; 1.1980x over previous
#include <cuda_runtime.h>
#include <cstdint>

// Scratch: per-node projection (pu0, pu1, pv0, pv1). 50000 * 16B = 800 KB.
#define MAX_NODES 131072
__device__ float4 g_node_proj[MAX_NODES];

#define D_DIM 128
#define E_DIM 64

// ---------------------------------------------------------------------------
// Kernel 1: proj[n] = (nf[n]@Wu, nf[n]@Wv). 16 lanes per node, register weights.
__global__ void node_proj_kernel(const float* __restrict__ nf,
                                 const float* __restrict__ W,  // [2D+E_DIM, 2]
                                 int n_nodes) {
    int gid = blockIdx.x * blockDim.x + threadIdx.x;
    int node = gid >> 4;
    int lane16 = gid & 15;
    bool valid = (node < n_nodes);

    const float2* W2 = reinterpret_cast<const float2*>(W);

    float4 wu_lo0 = *reinterpret_cast<const float4*>(&W2[4 * lane16]);
    float4 wu_lo1 = *reinterpret_cast<const float4*>(&W2[4 * lane16 + 2]);
    float4 wu_hi0 = *reinterpret_cast<const float4*>(&W2[64 + 4 * lane16]);
    float4 wu_hi1 = *reinterpret_cast<const float4*>(&W2[64 + 4 * lane16 + 2]);
    float4 wv_lo0 = *reinterpret_cast<const float4*>(&W2[128 + 4 * lane16]);
    float4 wv_lo1 = *reinterpret_cast<const float4*>(&W2[128 + 4 * lane16 + 2]);
    float4 wv_hi0 = *reinterpret_cast<const float4*>(&W2[192 + 4 * lane16]);
    float4 wv_hi1 = *reinterpret_cast<const float4*>(&W2[192 + 4 * lane16 + 2]);

    float4 a = make_float4(0.f, 0.f, 0.f, 0.f);
    float4 c = make_float4(0.f, 0.f, 0.f, 0.f);
    if (valid) {
        const float4* row = reinterpret_cast<const float4*>(nf + (size_t)node * D_DIM);
        a = __ldcs(row + lane16);
        c = __ldcs(row + lane16 + 16);
    }

    float pu0, pu1, pv0, pv1;
    pu0 = a.x * wu_lo0.x;            pu1 = a.x * wu_lo0.y;
    pv0 = a.x * wv_lo0.x;            pv1 = a.x * wv_lo0.y;
    pu0 = fmaf(a.y, wu_lo0.z, pu0);  pu1 = fmaf(a.y, wu_lo0.w, pu1);
    pv0 = fmaf(a.y, wv_lo0.z, pv0);  pv1 = fmaf(a.y, wv_lo0.w, pv1);
    pu0 = fmaf(a.z, wu_lo1.x, pu0);  pu1 = fmaf(a.z, wu_lo1.y, pu1);
    pv0 = fmaf(a.z, wv_lo1.x, pv0);  pv1 = fmaf(a.z, wv_lo1.y, pv1);
    pu0 = fmaf(a.w, wu_lo1.z, pu0);  pu1 = fmaf(a.w, wu_lo1.w, pu1);
    pv0 = fmaf(a.w, wv_lo1.z, pv0);  pv1 = fmaf(a.w, wv_lo1.w, pv1);
    pu0 = fmaf(c.x, wu_hi0.x, pu0);  pu1 = fmaf(c.x, wu_hi0.y, pu1);
    pv0 = fmaf(c.x, wv_hi0.x, pv0);  pv1 = fmaf(c.x, wv_hi0.y, pv1);
    pu0 = fmaf(c.y, wu_hi0.z, pu0);  pu1 = fmaf(c.y, wu_hi0.w, pu1);
    pv0 = fmaf(c.y, wv_hi0.z, pv0);  pv1 = fmaf(c.y, wv_hi0.w, pv1);
    pu0 = fmaf(c.z, wu_hi1.x, pu0);  pu1 = fmaf(c.z, wu_hi1.y, pu1);
    pv0 = fmaf(c.z, wv_hi1.x, pv0);  pv1 = fmaf(c.z, wv_hi1.y, pv1);
    pu0 = fmaf(c.w, wu_hi1.z, pu0);  pu1 = fmaf(c.w, wu_hi1.w, pu1);
    pv0 = fmaf(c.w, wv_hi1.z, pv0);  pv1 = fmaf(c.w, wv_hi1.w, pv1);

#pragma unroll
    for (int off = 8; off; off >>= 1) {
        pu0 += __shfl_xor_sync(0xffffffffu, pu0, off);
        pu1 += __shfl_xor_sync(0xffffffffu, pu1, off);
        pv0 += __shfl_xor_sync(0xffffffffu, pv0, off);
        pv1 += __shfl_xor_sync(0xffffffffu, pv1, off);
    }
    if (valid && lane16 == 0) g_node_proj[node] = make_float4(pu0, pu1, pv0, pv1);
}

// ---------------------------------------------------------------------------
// Kernel 2: 4 lanes per edge, 3-level pipeline, front-batched loads.
// out[e] = proj[src[e]].(x,y) + proj[dst[e]].(z,w) + ef[e]@We + b

__device__ __forceinline__ void dot16(float& s0, float& s1,
                                      const float4& v0, const float4& v1,
                                      const float4& v2, const float4& v3,
                                      const float2* __restrict__ w) {
    float x0, x1, y0, y1;
    x0 = v0.x * w[0].x;              x1 = v0.x * w[0].y;
    y0 = v2.x * w[8].x;              y1 = v2.x * w[8].y;
    x0 = fmaf(v0.y, w[1].x, x0);     x1 = fmaf(v0.y, w[1].y, x1);
    y0 = fmaf(v2.y, w[9].x, y0);     y1 = fmaf(v2.y, w[9].y, y1);
    x0 = fmaf(v0.z, w[2].x, x0);     x1 = fmaf(v0.z, w[2].y, x1);
    y0 = fmaf(v2.z, w[10].x, y0);    y1 = fmaf(v2.z, w[10].y, y1);
    x0 = fmaf(v0.w, w[3].x, x0);     x1 = fmaf(v0.w, w[3].y, x1);
    y0 = fmaf(v2.w, w[11].x, y0);    y1 = fmaf(v2.w, w[11].y, y1);
    x0 = fmaf(v1.x, w[4].x, x0);     x1 = fmaf(v1.x, w[4].y, x1);
    y0 = fmaf(v3.x, w[12].x, y0);    y1 = fmaf(v3.x, w[12].y, y1);
    x0 = fmaf(v1.y, w[5].x, x0);     x1 = fmaf(v1.y, w[5].y, x1);
    y0 = fmaf(v3.y, w[13].x, y0);    y1 = fmaf(v3.y, w[13].y, y1);
    x0 = fmaf(v1.z, w[6].x, x0);     x1 = fmaf(v1.z, w[6].y, x1);
    y0 = fmaf(v3.z, w[14].x, y0);    y1 = fmaf(v3.z, w[14].y, y1);
    x0 = fmaf(v1.w, w[7].x, x0);     x1 = fmaf(v1.w, w[7].y, x1);
    y0 = fmaf(v3.w, w[15].x, y0);    y1 = fmaf(v3.w, w[15].y, y1);
    s0 = x0 + y0;
    s1 = x1 + y1;
}

__global__ void edge_score_kernel(const float* __restrict__ ef,
                                  const int* __restrict__ src,
                                  const int* __restrict__ dst,
                                  const float* __restrict__ W,
                                  const float* __restrict__ b,
                                  float2* __restrict__ out,
                                  int n_edges) {
    const int lane4 = threadIdx.x & 3;
    const float2* W2 = reinterpret_cast<const float2*>(W);

    float2 w[16];
#pragma unroll
    for (int i = 0; i < 4; i++) {
        int kb = 2 * D_DIM + 4 * (lane4 + 4 * i);
        float4 p0 = *reinterpret_cast<const float4*>(&W2[kb]);
        float4 p1 = *reinterpret_cast<const float4*>(&W2[kb + 2]);
        w[4 * i + 0] = make_float2(p0.x, p0.y);
        w[4 * i + 1] = make_float2(p0.z, p0.w);
        w[4 * i + 2] = make_float2(p1.x, p1.y);
        w[4 * i + 3] = make_float2(p1.z, p1.w);
    }
    const float b0 = b[0], b1 = b[1];

    const int G = (gridDim.x * blockDim.x) >> 2;
    const int group = (blockIdx.x * blockDim.x + threadIdx.x) >> 2;
    const int last = n_edges - 1;

    int e = group;
    int wc = group & ~7;  // warp-uniform cursor

    // ---- Prologue ----
    // Stage 0 (current): ef + proj for edge e (gather exposed once, fine).
    int ec = e > last ? last : e;
    const float4* r0p = reinterpret_cast<const float4*>(ef) + (size_t)ec * 16 + lane4;
    float4 v0 = r0p[0], v1 = r0p[4], v2 = r0p[8], v3 = r0p[12];
    float2 pu, pv;
    {
        int si = src[ec], di = dst[ec];
        pu = *reinterpret_cast<const float2*>(&g_node_proj[si]);
        pv = *(reinterpret_cast<const float2*>(&g_node_proj[di]) + 1);
    }
    // Stage 1: indices for edge e+G (gathered at next loop top).
    int ec1 = (e + G) > last ? last : (e + G);
    int siN = src[ec1], diN = dst[ec1];

    while (wc < n_edges) {
        int eN = e + G;
        int ecN = eN > last ? last : eN;
        int ec2 = (e + 2 * G) > last ? last : (e + 2 * G);

        // ---- Front-batched prefetch: 4 ef + 2 gather + 2 idx ----
        const float4* rp = reinterpret_cast<const float4*>(ef) + (size_t)ecN * 16 + lane4;
        float4 m0 = rp[0];
        float4 m1 = rp[4];
        float4 m2 = rp[8];
        float4 m3 = rp[12];
        float2 puN = *reinterpret_cast<const float2*>(&g_node_proj[siN]);
        float2 pvN = *(reinterpret_cast<const float2*>(&g_node_proj[diN]) + 1);
        int siN2 = src[ec2];
        int diN2 = dst[ec2];

        // ---- Compute current edge e ----
        float s0, s1;
        dot16(s0, s1, v0, v1, v2, v3, w);
        s0 += __shfl_xor_sync(0xffffffffu, s0, 1);
        s1 += __shfl_xor_sync(0xffffffffu, s1, 1);
        s0 += __shfl_xor_sync(0xffffffffu, s0, 2);
        s1 += __shfl_xor_sync(0xffffffffu, s1, 2);
        if (lane4 == 0 && e < n_edges)
            out[e] = make_float2(s0 + pu.x + pv.x + b0,
                                 s1 + pu.y + pv.y + b1);

        // ---- Rotate pipeline ----
        v0 = m0; v1 = m1; v2 = m2; v3 = m3;
        pu = puN; pv = pvN;
        siN = siN2; diN = diN2;
        e = eN;
        wc += G;
    }
}

extern "C" void kernel_launch(void* const* d_in, const int* in_sizes, int n_in,
                              void* d_out, int out_size) {
    const float* node_feats = (const float*)d_in[0];
    const float* edge_feats = (const float*)d_in[1];
    const int*   src        = (const int*)d_in[2];
    const int*   dst        = (const int*)d_in[3];
    const float* W          = (const float*)d_in[4];
    const float* b          = (const float*)d_in[5];
    float2* out = (float2*)d_out;

    int n_nodes = in_sizes[0] / D_DIM;
    int n_edges = in_sizes[2];

    // Kernel 1: 16 lanes per node, 16 nodes per 256-thread block.
    {
        int threads = 256;
        int nodes_per_block = threads / 16;
        int blocks = (n_nodes + nodes_per_block - 1) / nodes_per_block;
        node_proj_kernel<<<blocks, threads>>>(node_feats, W, n_nodes);
    }

    // Kernel 2: 4 lanes per edge, pipelined grid-stride.
    {
        int threads = 256;
        int groups_per_block = threads / 4;
        int blocks = 1480;
        int max_blocks = (n_edges + groups_per_block - 1) / groups_per_block;
        if (blocks > max_blocks) blocks = max_blocks;
        edge_score_kernel<<<blocks, threads>>>(edge_feats, src, dst, W, b,
                                               out, n_edges);
    }
}